// round 1
// baseline (speedup 1.0000x reference)
#include <cuda_runtime.h>
#include <cstddef>

#define D_MODEL 1024
#define NHEAD   16
#define HEAD_DIM 64
#define BATCH   4
#define SEQ     2048
#define MTOT    (BATCH * SEQ)   // 8192

// Scratch buffers (device globals: allocation-free)
__device__ float g_Q[MTOT * D_MODEL];
__device__ float g_K[MTOT * D_MODEL];
__device__ float g_V[MTOT * D_MODEL];
__device__ float g_O[MTOT * D_MODEL];

// ---------------------------------------------------------------------------
// SGEMM with bias: C[M,N] = A[M,K] @ W[K,N] + bias[N]
// BM=BN=128, BK=8, 256 threads, 8x8 register tile per thread.
// Assumes M%128==0, N%128==0, K%8==0.
// ---------------------------------------------------------------------------
__global__ void __launch_bounds__(256) sgemm_bias(
    const float* __restrict__ A, const float* __restrict__ W,
    const float* __restrict__ bias, float* __restrict__ C,
    int M, int N, int K)
{
    const int BM = 128, BN = 128, BK = 8, TM = 8, TN = 8;
    __shared__ float As[BK][BM];
    __shared__ float Bs[BK][BN];

    const int tid = threadIdx.x;
    const int br  = blockIdx.y, bc = blockIdx.x;

    const float* Ab = A + (size_t)br * BM * K;
    const float* Wb = W + bc * BN;

    const int tr = tid >> 4;          // 0..15
    const int tc = tid & 15;          // 0..15

    float acc[TM][TN];
    #pragma unroll
    for (int i = 0; i < TM; i++)
        #pragma unroll
        for (int j = 0; j < TN; j++) acc[i][j] = 0.0f;

    const int aRow = tid >> 1;        // 0..127
    const int aCol = (tid & 1) * 4;   // 0 or 4
    const int bRow = tid >> 5;        // 0..7
    const int bCol = (tid & 31) * 4;  // 0..124

    for (int k0 = 0; k0 < K; k0 += BK) {
        float4 av = *(const float4*)(Ab + (size_t)aRow * K + k0 + aCol);
        As[aCol + 0][aRow] = av.x;
        As[aCol + 1][aRow] = av.y;
        As[aCol + 2][aRow] = av.z;
        As[aCol + 3][aRow] = av.w;
        *(float4*)&Bs[bRow][bCol] =
            *(const float4*)(Wb + (size_t)(k0 + bRow) * N + bCol);
        __syncthreads();

        #pragma unroll
        for (int k = 0; k < BK; k++) {
            float a[TM], b[TN];
            #pragma unroll
            for (int i = 0; i < TM; i++) a[i] = As[k][tr * TM + i];
            #pragma unroll
            for (int j = 0; j < TN; j++) b[j] = Bs[k][tc * TN + j];
            #pragma unroll
            for (int i = 0; i < TM; i++)
                #pragma unroll
                for (int j = 0; j < TN; j++) acc[i][j] += a[i] * b[j];
        }
        __syncthreads();
    }

    #pragma unroll
    for (int i = 0; i < TM; i++) {
        const int row = br * BM + tr * TM + i;
        #pragma unroll
        for (int j = 0; j < TN; j += 4) {
            const int col = bc * BN + tc * TN + j;
            float4 o;
            o.x = acc[i][j + 0] + bias[col + 0];
            o.y = acc[i][j + 1] + bias[col + 1];
            o.z = acc[i][j + 2] + bias[col + 2];
            o.w = acc[i][j + 3] + bias[col + 3];
            *(float4*)(C + (size_t)row * N + col) = o;
        }
    }
}

// ---------------------------------------------------------------------------
// Flash attention (fp32). Grid: (S/64, B*H). 256 threads.
// Each block: 64 queries of one (b,h). Iterates over 32 key tiles of 64.
// Thread layout: qg = t>>3 owns queries {2qg, 2qg+1}; sub = t&7 owns
// key-columns {sub + 8*jj} and dim-columns {sub + 8*i}.
// smem strides: 68 for Q/K/V (bank-conflict-free for strided sub access),
// 65 for the P matrix.
// ---------------------------------------------------------------------------
#define QKV_STRIDE 68
#define P_STRIDE   65
#define ATTN_SMEM_FLOATS (3 * 64 * QKV_STRIDE + 64 * P_STRIDE)
#define ATTN_SMEM_BYTES  (ATTN_SMEM_FLOATS * 4)

__global__ void __launch_bounds__(256) attn_kernel(
    const float* __restrict__ gQ, const float* __restrict__ gK,
    const float* __restrict__ gV, float* __restrict__ gO)
{
    extern __shared__ float sm[];
    float* Qs = sm;                          // 64 x 68
    float* Ks = Qs + 64 * QKV_STRIDE;        // 64 x 68
    float* Vs = Ks + 64 * QKV_STRIDE;        // 64 x 68
    float* Ps = Vs + 64 * QKV_STRIDE;        // 64 x 65

    const int t  = threadIdx.x;
    const int bh = blockIdx.y;               // b*NHEAD + h
    const int b  = bh >> 4;
    const int h  = bh & 15;
    const int qt = blockIdx.x;               // 0..31

    const int sub = t & 7;
    const int qg  = t >> 3;
    const int q0  = 2 * qg, q1 = q0 + 1;

    // Load Q tile once
    {
        const int r  = t >> 2;               // 0..63
        const int c0 = (t & 3) * 16;
        const float* src =
            gQ + ((size_t)(b * SEQ + qt * 64 + r)) * D_MODEL + h * HEAD_DIM + c0;
        #pragma unroll
        for (int c = 0; c < 16; c += 4)
            *(float4*)&Qs[r * QKV_STRIDE + c0 + c] = *(const float4*)(src + c);
    }

    float o0[8], o1[8];
    #pragma unroll
    for (int i = 0; i < 8; i++) { o0[i] = 0.0f; o1[i] = 0.0f; }
    float m0 = -1e30f, m1 = -1e30f, l0 = 0.0f, l1 = 0.0f;

    __syncthreads();

    for (int kt = 0; kt < SEQ / 64; kt++) {
        // Load K and V tiles
        {
            const int r  = t >> 2;
            const int c0 = (t & 3) * 16;
            const size_t base =
                ((size_t)(b * SEQ + kt * 64 + r)) * D_MODEL + h * HEAD_DIM + c0;
            const float* sk = gK + base;
            const float* sv = gV + base;
            #pragma unroll
            for (int c = 0; c < 16; c += 4) {
                *(float4*)&Ks[r * QKV_STRIDE + c0 + c] = *(const float4*)(sk + c);
                *(float4*)&Vs[r * QKV_STRIDE + c0 + c] = *(const float4*)(sv + c);
            }
        }
        __syncthreads();

        // Scores: acc[jj] = Q[q] . K[sub + 8*jj]
        float acc0[8], acc1[8];
        #pragma unroll
        for (int jj = 0; jj < 8; jj++) { acc0[jj] = 0.0f; acc1[jj] = 0.0f; }

        #pragma unroll 4
        for (int d = 0; d < HEAD_DIM; d++) {
            const float qa = Qs[q0 * QKV_STRIDE + d];
            const float qb = Qs[q1 * QKV_STRIDE + d];
            #pragma unroll
            for (int jj = 0; jj < 8; jj++) {
                const float kv = Ks[(sub + 8 * jj) * QKV_STRIDE + d];
                acc0[jj] += qa * kv;
                acc1[jj] += qb * kv;
            }
        }

        const float scale = 0.125f;  // 1/sqrt(64)
        float tm0 = -1e30f, tm1 = -1e30f;
        #pragma unroll
        for (int jj = 0; jj < 8; jj++) {
            acc0[jj] *= scale; acc1[jj] *= scale;
            tm0 = fmaxf(tm0, acc0[jj]);
            tm1 = fmaxf(tm1, acc1[jj]);
        }
        #pragma unroll
        for (int s = 1; s < 8; s <<= 1) {
            tm0 = fmaxf(tm0, __shfl_xor_sync(0xffffffffu, tm0, s));
            tm1 = fmaxf(tm1, __shfl_xor_sync(0xffffffffu, tm1, s));
        }
        const float nm0 = fmaxf(m0, tm0);
        const float nm1 = fmaxf(m1, tm1);
        const float c0f = __expf(m0 - nm0);
        const float c1f = __expf(m1 - nm1);

        float ts0 = 0.0f, ts1 = 0.0f;
        #pragma unroll
        for (int jj = 0; jj < 8; jj++) {
            const float p0 = __expf(acc0[jj] - nm0);
            const float p1 = __expf(acc1[jj] - nm1);
            Ps[q0 * P_STRIDE + sub + 8 * jj] = p0;
            Ps[q1 * P_STRIDE + sub + 8 * jj] = p1;
            ts0 += p0; ts1 += p1;
        }
        #pragma unroll
        for (int s = 1; s < 8; s <<= 1) {
            ts0 += __shfl_xor_sync(0xffffffffu, ts0, s);
            ts1 += __shfl_xor_sync(0xffffffffu, ts1, s);
        }
        l0 = l0 * c0f + ts0;
        l1 = l1 * c1f + ts1;
        m0 = nm0; m1 = nm1;

        #pragma unroll
        for (int i = 0; i < 8; i++) { o0[i] *= c0f; o1[i] *= c1f; }

        __syncwarp();   // Ps rows q0/q1 produced entirely within this warp

        // O += P @ V
        #pragma unroll 4
        for (int j = 0; j < 64; j++) {
            const float p0 = Ps[q0 * P_STRIDE + j];
            const float p1 = Ps[q1 * P_STRIDE + j];
            #pragma unroll
            for (int i = 0; i < 8; i++) {
                const float vv = Vs[j * QKV_STRIDE + sub + 8 * i];
                o0[i] += p0 * vv;
                o1[i] += p1 * vv;
            }
        }
        __syncthreads();
    }

    const float r0 = 1.0f / l0;
    const float r1 = 1.0f / l1;
    const size_t out0 =
        ((size_t)(b * SEQ + qt * 64 + q0)) * D_MODEL + h * HEAD_DIM;
    const size_t out1 = out0 + D_MODEL;
    #pragma unroll
    for (int i = 0; i < 8; i++) {
        gO[out0 + sub + 8 * i] = o0[i] * r0;
        gO[out1 + sub + 8 * i] = o1[i] * r1;
    }
}

// ---------------------------------------------------------------------------
extern "C" void kernel_launch(void* const* d_in, const int* in_sizes, int n_in,
                              void* d_out, int out_size)
{
    const float* x  = (const float*)d_in[0];
    const float* y  = (const float*)d_in[1];
    const float* wq = (const float*)d_in[2];
    const float* bq = (const float*)d_in[3];
    const float* wk = (const float*)d_in[4];
    const float* bk = (const float*)d_in[5];
    const float* wv = (const float*)d_in[6];
    const float* bv = (const float*)d_in[7];
    const float* wo = (const float*)d_in[8];
    const float* bo = (const float*)d_in[9];
    float* out = (float*)d_out;

    float *Qp, *Kp, *Vp, *Op;
    cudaGetSymbolAddress((void**)&Qp, g_Q);
    cudaGetSymbolAddress((void**)&Kp, g_K);
    cudaGetSymbolAddress((void**)&Vp, g_V);
    cudaGetSymbolAddress((void**)&Op, g_O);

    cudaFuncSetAttribute(attn_kernel,
                         cudaFuncAttributeMaxDynamicSharedMemorySize,
                         ATTN_SMEM_BYTES);

    const dim3 gemm_grid(D_MODEL / 128, MTOT / 128);  // (8, 64)
    sgemm_bias<<<gemm_grid, 256>>>(x, wq, bq, Qp, MTOT, D_MODEL, D_MODEL);
    sgemm_bias<<<gemm_grid, 256>>>(y, wk, bk, Kp, MTOT, D_MODEL, D_MODEL);
    sgemm_bias<<<gemm_grid, 256>>>(y, wv, bv, Vp, MTOT, D_MODEL, D_MODEL);

    const dim3 attn_grid(SEQ / 64, BATCH * NHEAD);    // (32, 64)
    attn_kernel<<<attn_grid, 256, ATTN_SMEM_BYTES>>>(Qp, Kp, Vp, Op);

    sgemm_bias<<<gemm_grid, 256>>>(Op, wo, bo, out, MTOT, D_MODEL, D_MODEL);
}